// round 5
// baseline (speedup 1.0000x reference)
#include <cuda_runtime.h>

#define M_DIM 1024
#define N_DIM 512
#define K_DIM 33154
#define C1 16641          // end of st region
#define C2 16770          // end of at region (16641+129)
#define OUTD 129
#define BM 128
#define BN 128
#define BK 16
#define SPLITS 9
#define KT_TOTAL 2073     // ceil(33154/16)
#define KT_PER 231        // ceil(2073/9)
#define LDSH 136          // padded smem row stride (floats): conflict-free frag loads

__device__ float g_part[SPLITS * M_DIM * N_DIM];   // 18 MB split-K partials
__device__ float g_h[M_DIM * N_DIM];               // hidden activations

__device__ __forceinline__ unsigned smem_u32(const void* p) {
    return (unsigned)__cvta_generic_to_shared(p);
}
__device__ __forceinline__ void cp4(unsigned dst, const void* src, bool v) {
    int sz = v ? 4 : 0;
    asm volatile("cp.async.ca.shared.global [%0], [%1], 4, %2;\n" :: "r"(dst), "l"(src), "r"(sz));
}
__device__ __forceinline__ void cp16(unsigned dst, const void* src, bool v) {
    int sz = v ? 16 : 0;
    asm volatile("cp.async.cg.shared.global [%0], [%1], 16, %2;\n" :: "r"(dst), "l"(src), "r"(sz));
}
// round fp32 toward nearest tf32 (HW truncates low 13 bits; +0x1000 = round-half-up, unbiased to 1st order)
__device__ __forceinline__ unsigned rtf(float x) { return __float_as_uint(x) + 0x1000u; }

__device__ __forceinline__ void mma_tf32(float c[4], unsigned a0, unsigned a1, unsigned a2, unsigned a3,
                                         unsigned b0, unsigned b1) {
    asm volatile("mma.sync.aligned.m16n8k8.row.col.f32.tf32.tf32.f32 "
                 "{%0,%1,%2,%3}, {%4,%5,%6,%7}, {%8,%9}, {%0,%1,%2,%3};\n"
                 : "+f"(c[0]), "+f"(c[1]), "+f"(c[2]), "+f"(c[3])
                 : "r"(a0), "r"(a1), "r"(a2), "r"(a3), "r"(b0), "r"(b1));
}

// ---------------- GEMM1: partial[split] = Xchunk @ W1chunk (tf32 MMA, split-K) ----------------
__global__ __launch_bounds__(256, 2)
void gemm1_kernel(const float* __restrict__ st, const float* __restrict__ at,
                  const float* __restrict__ st1, const float* __restrict__ W1) {
    __shared__ float As[2][BK][LDSH];
    __shared__ float Bs[2][BK][LDSH];

    const int tid  = threadIdx.x;
    const int lane = tid & 31;
    const int warp = tid >> 5;
    const int gid  = lane >> 2;     // groupID
    const int tig  = lane & 3;      // threadID_in_group
    const int wm   = (warp >> 2) * 64;   // warp m offset (2 rows of warps)
    const int wn   = (warp & 3) * 32;    // warp n offset (4 cols of warps)

    const int m_blk = blockIdx.y * BM;
    const int n_blk = blockIdx.x * BN;
    const int split = blockIdx.z;
    const int kt0 = split * KT_PER;
    const int kt1 = min(kt0 + KT_PER, KT_TOTAL);
    const int nkt = kt1 - kt0;

    // A loader mapping: thread -> (m = tid&127, k parity = tid>>7), 8 elements each
    const int a_m  = tid & 127;
    const int a_k0 = tid >> 7;
    const int mg   = m_blk + a_m;
    const float* row_st  = st  + (size_t)mg * C1;
    const float* row_at  = at  + (size_t)mg * 129;
    const float* row_st1 = st1 + (size_t)mg * 16384;

    auto load_tile = [&](int buf, int kt) {
        const int kgb = kt * BK;
        // ---- A (gathered concat; fast path when whole window is in one region) ----
        if (kgb + BK <= C1) {
            const float* base = row_st + kgb + a_k0;
            #pragma unroll
            for (int kk = 0; kk < 8; kk++)
                cp4(smem_u32(&As[buf][kk * 2 + a_k0][a_m]), base + kk * 2, true);
        } else if (kgb >= C2 && kgb + BK <= K_DIM) {
            const float* base = row_st1 + (kgb - C2) + a_k0;
            #pragma unroll
            for (int kk = 0; kk < 8; kk++)
                cp4(smem_u32(&As[buf][kk * 2 + a_k0][a_m]), base + kk * 2, true);
        } else {
            #pragma unroll
            for (int kk = 0; kk < 8; kk++) {
                const int kl = kk * 2 + a_k0;
                const int kg = kgb + kl;
                const float* p; bool v = true;
                if (kg < C1)           p = row_st  + kg;
                else if (kg < C2)      p = row_at  + (kg - C1);
                else if (kg < K_DIM)   p = row_st1 + (kg - C2);
                else                 { p = row_st; v = false; }
                cp4(smem_u32(&As[buf][kl][a_m]), p, v);
            }
        }
        // ---- B (W1 rows are contiguous, 16B vectorized) ----
        #pragma unroll
        for (int q = 0; q < 2; q++) {
            const int idx = tid * 2 + q;          // 0..511 float4s
            const int kl  = idx >> 5;
            const int n   = (idx & 31) * 4;
            const int kg  = kgb + kl;
            const bool v  = kg < K_DIM;
            const float* p = W1 + (size_t)(v ? kg : 0) * N_DIM + n_blk + n;
            cp16(smem_u32(&Bs[buf][kl][n]), p, v);
        }
    };

    float c[4][4][4];
    #pragma unroll
    for (int i = 0; i < 4; i++)
        #pragma unroll
        for (int j = 0; j < 4; j++)
            #pragma unroll
            for (int q = 0; q < 4; q++) c[i][j][q] = 0.f;

    auto compute = [&](int buf) {
        #pragma unroll
        for (int ks = 0; ks < 2; ks++) {
            const int k0 = ks * 8;
            unsigned a[4][4], b[4][2];
            #pragma unroll
            for (int i = 0; i < 4; i++) {
                const int m0 = wm + i * 16;
                a[i][0] = rtf(As[buf][k0 + tig    ][m0 + gid    ]);
                a[i][1] = rtf(As[buf][k0 + tig    ][m0 + gid + 8]);
                a[i][2] = rtf(As[buf][k0 + tig + 4][m0 + gid    ]);
                a[i][3] = rtf(As[buf][k0 + tig + 4][m0 + gid + 8]);
            }
            #pragma unroll
            for (int j = 0; j < 4; j++) {
                const int n0 = wn + j * 8;
                b[j][0] = rtf(Bs[buf][k0 + tig    ][n0 + gid]);
                b[j][1] = rtf(Bs[buf][k0 + tig + 4][n0 + gid]);
            }
            #pragma unroll
            for (int i = 0; i < 4; i++)
                #pragma unroll
                for (int j = 0; j < 4; j++)
                    mma_tf32(c[i][j], a[i][0], a[i][1], a[i][2], a[i][3], b[j][0], b[j][1]);
        }
    };

    load_tile(0, kt0);
    asm volatile("cp.async.commit_group;\n");
    for (int it = 0; it < nkt; it++) {
        asm volatile("cp.async.wait_group 0;\n");
        __syncthreads();
        if (it + 1 < nkt) {
            load_tile((it + 1) & 1, kt0 + it + 1);
            asm volatile("cp.async.commit_group;\n");
        }
        compute(it & 1);
    }

    float* outp = g_part + (size_t)split * (M_DIM * N_DIM);
    #pragma unroll
    for (int i = 0; i < 4; i++) {
        const int mrow = m_blk + wm + i * 16 + gid;
        #pragma unroll
        for (int j = 0; j < 4; j++) {
            const int ncol = n_blk + wn + j * 8 + tig * 2;
            *(float2*)&outp[(size_t)mrow * N_DIM + ncol]       = make_float2(c[i][j][0], c[i][j][1]);
            *(float2*)&outp[(size_t)(mrow + 8) * N_DIM + ncol] = make_float2(c[i][j][2], c[i][j][3]);
        }
    }
}

// ---------------- reduce split-K partials + bias + ReLU -> g_h ----------------
__global__ void reduce_relu_kernel(const float* __restrict__ b1) {
    const int idx = blockIdx.x * blockDim.x + threadIdx.x;   // over M*N/4 float4s
    const float4* p = (const float4*)g_part;
    float4 acc = p[idx];
    #pragma unroll
    for (int s = 1; s < SPLITS; s++) {
        float4 v = p[idx + s * (M_DIM * N_DIM / 4)];
        acc.x += v.x; acc.y += v.y; acc.z += v.z; acc.w += v.w;
    }
    const float4 bb = ((const float4*)b1)[idx & 127];
    acc.x = fmaxf(acc.x + bb.x, 0.f);
    acc.y = fmaxf(acc.y + bb.y, 0.f);
    acc.z = fmaxf(acc.z + bb.z, 0.f);
    acc.w = fmaxf(acc.w + bb.w, 0.f);
    ((float4*)g_h)[idx] = acc;
}

// ---------------- GEMM2: out = relu_h @ W2 + b2 (fp32) ----------------
__global__ __launch_bounds__(258)
void gemm2_kernel(const float* __restrict__ W2, const float* __restrict__ b2,
                  float* __restrict__ out) {
    __shared__ float hs[4 * N_DIM];
    const int mb = blockIdx.x * 4;
    for (int i = threadIdx.x; i < 4 * N_DIM; i += 258)
        hs[i] = g_h[(size_t)mb * N_DIM + i];
    __syncthreads();

    const int t  = threadIdx.x;          // 0..257
    const int rr = t / OUTD;             // 0 or 1
    const int o  = t - rr * OUTD;        // 0..128
    float acc0 = 0.f, acc1 = 0.f;
    const float* h0 = hs + rr * N_DIM;
    const float* h1 = hs + (rr + 2) * N_DIM;
    #pragma unroll 8
    for (int k = 0; k < N_DIM; k++) {
        const float w = W2[k * OUTD + o];
        acc0 = fmaf(h0[k], w, acc0);
        acc1 = fmaf(h1[k], w, acc1);
    }
    const float bias = b2[o];
    out[(size_t)(mb + rr) * OUTD + o]     = acc0 + bias;
    out[(size_t)(mb + rr + 2) * OUTD + o] = acc1 + bias;
}

extern "C" void kernel_launch(void* const* d_in, const int* in_sizes, int n_in,
                              void* d_out, int out_size) {
    const float* st  = (const float*)d_in[0];
    const float* at  = (const float*)d_in[1];
    const float* st1 = (const float*)d_in[2];
    const float* W1  = (const float*)d_in[3];
    const float* b1  = (const float*)d_in[4];
    const float* W2  = (const float*)d_in[5];
    const float* b2  = (const float*)d_in[6];
    (void)in_sizes; (void)n_in; (void)out_size;

    dim3 g1(N_DIM / BN, M_DIM / BM, SPLITS);     // 4 x 8 x 9 = 288 CTAs
    gemm1_kernel<<<g1, 256>>>(st, at, st1, W1);
    reduce_relu_kernel<<<(M_DIM * N_DIM / 4) / 256, 256>>>(b1);
    gemm2_kernel<<<M_DIM / 4, 258>>>(W2, b2, (float*)d_out);
}

// round 9
// speedup vs baseline: 3.0563x; 3.0563x over previous
#include <cuda_runtime.h>

#define M_DIM 1024
#define N_DIM 512
#define K_DIM 33154
#define C1 16641          // end of st region
#define C2 16770          // end of at region (16641+129)
#define OUTD 129
#define BM 128
#define BN 128
#define BK 16
#define SPLITS 9
#define KT_TOTAL 2073     // ceil(33154/16)
#define KT_PER 231        // ceil(2073/9)
#define LDSH 136          // padded smem row stride (floats): conflict-free frag loads
#define KPAD 33184        // 1037 * 32, covers KT_TOTAL*16 = 33168
#define NSTAGE 4

__device__ unsigned g_Xt[(size_t)KPAD * M_DIM];    // 135.9 MB: X^T, pre-rounded tf32 bits
__device__ float g_part[SPLITS * M_DIM * N_DIM];   // 18 MB split-K partials

__device__ __forceinline__ unsigned smem_u32(const void* p) {
    return (unsigned)__cvta_generic_to_shared(p);
}
__device__ __forceinline__ void cp16(unsigned dst, const void* src, bool v) {
    int sz = v ? 16 : 0;
    asm volatile("cp.async.cg.shared.global [%0], [%1], 16, %2;\n" :: "r"(dst), "l"(src), "r"(sz));
}
// round fp32 toward nearest tf32 (HW truncates low 13 bits; +0x1000 = round-half-up)
__device__ __forceinline__ unsigned rtf(float x) { return __float_as_uint(x) + 0x1000u; }

__device__ __forceinline__ void mma_tf32(float c[4], unsigned a0, unsigned a1, unsigned a2, unsigned a3,
                                         unsigned b0, unsigned b1) {
    asm volatile("mma.sync.aligned.m16n8k8.row.col.f32.tf32.tf32.f32 "
                 "{%0,%1,%2,%3}, {%4,%5,%6,%7}, {%8,%9}, {%0,%1,%2,%3};\n"
                 : "+f"(c[0]), "+f"(c[1]), "+f"(c[2]), "+f"(c[3])
                 : "r"(a0), "r"(a1), "r"(a2), "r"(a3), "r"(b0), "r"(b1));
}

// ---------------- gather concat + transpose + tf32-round: X[m][k] -> g_Xt[k][m] ----------------
__global__ __launch_bounds__(256)
void transpose_kernel(const float* __restrict__ st, const float* __restrict__ at,
                      const float* __restrict__ st1) {
    __shared__ unsigned s[32][33];
    const int tx = threadIdx.x & 31;
    const int ty = threadIdx.x >> 5;              // 0..7
    const int m0 = blockIdx.x * 32;
    const int k0 = blockIdx.y * 32;

    #pragma unroll
    for (int r = 0; r < 4; r++) {
        const int m = m0 + ty + r * 8;
        const int k = k0 + tx;
        unsigned u = 0u;
        if (k < C1)        u = rtf(st [(size_t)m * C1    + k]);
        else if (k < C2)   u = rtf(at [(size_t)m * 129   + (k - C1)]);
        else if (k < K_DIM)u = rtf(st1[(size_t)m * 16384 + (k - C2)]);
        s[ty + r * 8][tx] = u;
    }
    __syncthreads();
    #pragma unroll
    for (int r = 0; r < 4; r++) {
        const int k = k0 + ty + r * 8;
        const int m = m0 + tx;
        g_Xt[(size_t)k * M_DIM + m] = s[tx][ty + r * 8];
    }
}

// ---------------- GEMM1: partial[split] = Xchunk @ W1chunk (tf32 MMA, split-K) ----------------
__global__ __launch_bounds__(256, 2)
void gemm1_kernel(const float* __restrict__ W1) {
    extern __shared__ unsigned char smem_raw[];
    unsigned (*As)[BK][LDSH] = (unsigned (*)[BK][LDSH])smem_raw;
    float    (*Bs)[BK][LDSH] = (float    (*)[BK][LDSH])(smem_raw + NSTAGE * BK * LDSH * 4);

    const int tid  = threadIdx.x;
    const int lane = tid & 31;
    const int warp = tid >> 5;
    const int gid  = lane >> 2;          // groupID
    const int tig  = lane & 3;           // threadID_in_group
    const int wm   = (warp >> 2) * 64;   // warp m offset
    const int wn   = (warp & 3) * 32;    // warp n offset

    const int m_blk = blockIdx.y * BM;
    const int n_blk = blockIdx.x * BN;
    const int split = blockIdx.z;
    const int kt0 = split * KT_PER;
    const int kt1 = min(kt0 + KT_PER, KT_TOTAL);
    const int nkt = kt1 - kt0;

    auto load_tile = [&](int buf, int kt) {
        const int kgb = kt * BK;
        // ---- A from g_Xt[k][m]: fully coalesced 16B cp.async, no bounds checks (padded) ----
        #pragma unroll
        for (int q = 0; q < 2; q++) {
            const int idx = q * 256 + tid;        // 0..511 float4s
            const int kl  = idx >> 5;
            const int m4  = (idx & 31) * 4;
            cp16(smem_u32(&As[buf][kl][m4]),
                 g_Xt + (size_t)(kgb + kl) * M_DIM + m_blk + m4, true);
        }
        // ---- B (W1 rows contiguous, 16B, zero-fill past K) ----
        #pragma unroll
        for (int q = 0; q < 2; q++) {
            const int idx = q * 256 + tid;
            const int kl  = idx >> 5;
            const int n   = (idx & 31) * 4;
            const int kg  = kgb + kl;
            const bool v  = kg < K_DIM;
            const float* p = W1 + (size_t)(v ? kg : 0) * N_DIM + n_blk + n;
            cp16(smem_u32(&Bs[buf][kl][n]), p, v);
        }
    };

    float c[4][4][4];
    #pragma unroll
    for (int i = 0; i < 4; i++)
        #pragma unroll
        for (int j = 0; j < 4; j++)
            #pragma unroll
            for (int q = 0; q < 4; q++) c[i][j][q] = 0.f;

    auto compute = [&](int buf) {
        #pragma unroll
        for (int ks = 0; ks < 2; ks++) {
            const int k0 = ks * 8;
            unsigned a[4][4], b[4][2];
            #pragma unroll
            for (int i = 0; i < 4; i++) {
                const int m0 = wm + i * 16;
                a[i][0] = As[buf][k0 + tig    ][m0 + gid    ];
                a[i][1] = As[buf][k0 + tig    ][m0 + gid + 8];
                a[i][2] = As[buf][k0 + tig + 4][m0 + gid    ];
                a[i][3] = As[buf][k0 + tig + 4][m0 + gid + 8];
            }
            #pragma unroll
            for (int j = 0; j < 4; j++) {
                const int n0 = wn + j * 8;
                b[j][0] = rtf(Bs[buf][k0 + tig    ][n0 + gid]);
                b[j][1] = rtf(Bs[buf][k0 + tig + 4][n0 + gid]);
            }
            #pragma unroll
            for (int i = 0; i < 4; i++)
                #pragma unroll
                for (int j = 0; j < 4; j++)
                    mma_tf32(c[i][j], a[i][0], a[i][1], a[i][2], a[i][3], b[j][0], b[j][1]);
        }
    };

    // 4-stage pipeline: prologue fills 3 stages, each iter keeps up to 2 groups in flight
    #pragma unroll
    for (int s = 0; s < NSTAGE - 1; s++) {
        load_tile(s, kt0 + s);                    // nkt >= 225 always, no guard needed
        asm volatile("cp.async.commit_group;\n");
    }
    for (int it = 0; it < nkt; it++) {
        asm volatile("cp.async.wait_group 2;\n");
        __syncthreads();
        if (it + NSTAGE - 1 < nkt)
            load_tile((it + NSTAGE - 1) & (NSTAGE - 1), kt0 + it + NSTAGE - 1);
        asm volatile("cp.async.commit_group;\n"); // unconditional: keeps group count aligned
        compute(it & (NSTAGE - 1));
    }

    float* outp = g_part + (size_t)split * (M_DIM * N_DIM);
    #pragma unroll
    for (int i = 0; i < 4; i++) {
        const int mrow = m_blk + wm + i * 16 + gid;
        #pragma unroll
        for (int j = 0; j < 4; j++) {
            const int ncol = n_blk + wn + j * 8 + tig * 2;
            *(float2*)&outp[(size_t)mrow * N_DIM + ncol]       = make_float2(c[i][j][0], c[i][j][1]);
            *(float2*)&outp[(size_t)(mrow + 8) * N_DIM + ncol] = make_float2(c[i][j][2], c[i][j][3]);
        }
    }
}

// ---------------- fused: reduce split-K + bias + ReLU + GEMM2 (+b2) -> out ----------------
__global__ __launch_bounds__(258)
void gemm2_kernel(const float* __restrict__ b1, const float* __restrict__ W2,
                  const float* __restrict__ b2, float* __restrict__ out) {
    __shared__ float hs[N_DIM * 8];               // 8 rows, k-major interleaved
    const int mb = blockIdx.x * 8;

    // Phase 1: 9-way split-K reduce + bias + relu into smem
    for (int i = threadIdx.x; i < 8 * N_DIM; i += 258) {
        const int row = i >> 9;                   // 0..7
        const int col = i & 511;
        float a = 0.f;
        #pragma unroll
        for (int s = 0; s < SPLITS; s++)
            a += g_part[((size_t)s * M_DIM + mb + row) * N_DIM + col];
        a = fmaxf(a + b1[col], 0.f);
        // layout: hs[col*8 + (row&1)*4 + (row>>1)] -> rows {rr, rr+2, rr+4, rr+6} contiguous
        hs[col * 8 + (row & 1) * 4 + (row >> 1)] = a;
    }
    __syncthreads();

    // Phase 2: each thread = (rr, o), 4 row-accumulators, float4 h loads
    const int t  = threadIdx.x;                   // 0..257
    const int rr = t / OUTD;                      // 0 or 1
    const int o  = t - rr * OUTD;                 // 0..128
    float acc0 = 0.f, acc1 = 0.f, acc2 = 0.f, acc3 = 0.f;
    #pragma unroll 4
    for (int k = 0; k < N_DIM; k++) {
        const float w = W2[k * OUTD + o];
        const float4 h4 = *(const float4*)&hs[k * 8 + rr * 4];
        acc0 = fmaf(h4.x, w, acc0);
        acc1 = fmaf(h4.y, w, acc1);
        acc2 = fmaf(h4.z, w, acc2);
        acc3 = fmaf(h4.w, w, acc3);
    }
    const float bias = b2[o];
    out[(size_t)(mb + rr    ) * OUTD + o] = acc0 + bias;
    out[(size_t)(mb + rr + 2) * OUTD + o] = acc1 + bias;
    out[(size_t)(mb + rr + 4) * OUTD + o] = acc2 + bias;
    out[(size_t)(mb + rr + 6) * OUTD + o] = acc3 + bias;
}

extern "C" void kernel_launch(void* const* d_in, const int* in_sizes, int n_in,
                              void* d_out, int out_size) {
    const float* st  = (const float*)d_in[0];
    const float* at  = (const float*)d_in[1];
    const float* st1 = (const float*)d_in[2];
    const float* W1  = (const float*)d_in[3];
    const float* b1  = (const float*)d_in[4];
    const float* W2  = (const float*)d_in[5];
    const float* b2  = (const float*)d_in[6];
    (void)in_sizes; (void)n_in; (void)out_size;

    const int smem1 = NSTAGE * BK * LDSH * 4 * 2;           // 69632 B
    cudaFuncSetAttribute(gemm1_kernel, cudaFuncAttributeMaxDynamicSharedMemorySize, smem1);

    dim3 gt(M_DIM / 32, KPAD / 32);                         // 32 x 1037
    transpose_kernel<<<gt, 256>>>(st, at, st1);

    dim3 g1(N_DIM / BN, M_DIM / BM, SPLITS);                // 4 x 8 x 9 = 288 CTAs
    gemm1_kernel<<<g1, 256, smem1>>>(W1);

    gemm2_kernel<<<M_DIM / 8, 258>>>(b1, W2, b2, (float*)d_out);
}